// round 12
// baseline (speedup 1.0000x reference)
#include <cuda_runtime.h>
#include <math.h>
#include <stdint.h>

#define N_LINES 1200
#define SAMP 5
#define NPTS (N_LINES*SAMP)     // 6000
#define DIM 128
#define HH 128
#define WW 128
#define TOPK 10
#define CAND 16
#define GAPC 0.1f
#define BT 16                    // lines per block edge
#define KC 32                    // K chunk
#define CPITCH 84                // words per k-row (80 + 4 pad), 16B-aligned

// ---------------- device scratch ----------------
__device__ float g_desc1t[HH*WW*DIM];   // [y][x][d]
__device__ float g_desc2t[HH*WW*DIM];
__device__ float g_d1[NPTS*DIM];        // [pt][d] row-major (refine/nw)
__device__ float g_d2[NPTS*DIM];
__device__ float g_d1T[DIM*NPTS];       // [d][pt] transposed (linescore cp.async)
__device__ float g_d2T[DIM*NPTS];
__device__ int   g_ns1[N_LINES];
__device__ int   g_ns2[N_LINES];
__device__ float g_ls [N_LINES*N_LINES];
__device__ float g_lsT[N_LINES*N_LINES];
__device__ int   g_candf[N_LINES*CAND];
__device__ int   g_candr[N_LINES*CAND];
__device__ int   g_topkf[N_LINES*TOPK];
__device__ int   g_topkr[N_LINES*TOPK];
__device__ float g_nwf[N_LINES*2*TOPK];
__device__ float g_nwr[N_LINES*2*TOPK];
__device__ int   g_mf[N_LINES];
__device__ int   g_mr[N_LINES];

__device__ __forceinline__ uint32_t smem_u32(const void* p) {
    uint32_t a;
    asm("{ .reg .u64 t; cvta.to.shared.u64 t, %1; cvt.u32.u64 %0, t; }" : "=r"(a) : "l"(p));
    return a;
}
#define CP_ASYNC16(dst, src) \
    asm volatile("cp.async.cg.shared.global [%0], [%1], 16;" :: "r"(dst), "l"(src) : "memory")
#define CP_COMMIT() asm volatile("cp.async.commit_group;" ::: "memory")
#define CP_WAIT0()  asm volatile("cp.async.wait_group 0;" ::: "memory")
#define CP_WAIT1()  asm volatile("cp.async.wait_group 1;" ::: "memory")

// ---------------- transpose desc [d][y][x] -> [y][x][d] (both images) ----------------
__global__ void transpose_desc(const float* __restrict__ in1, const float* __restrict__ in2) {
    int idx = blockIdx.x * blockDim.x + threadIdx.x;
    int which = idx >= HH*WW*DIM;
    int i = which ? idx - HH*WW*DIM : idx;
    const float* in = which ? in2 : in1;
    int d = i % DIM;
    int x = (i / DIM) % WW;
    int y = i / (DIM*WW);
    float v = in[d*(HH*WW) + y*WW + x];
    if (which == 0) g_desc1t[i] = v; else g_desc2t[i] = v;
}

// ---------------- sample points + bilinear descriptors + normalize ----------------
__global__ void sample_kernel(const float* __restrict__ seg, int which) {
    int pid  = blockIdx.x;            // 0..NPTS-1
    int line = pid / SAMP;
    int k    = pid % SAMP;
    int d    = threadIdx.x;           // 0..127

    float s0 = seg[line*4+0], s1 = seg[line*4+1];
    float e0 = seg[line*4+2], e1 = seg[line*4+3];
    float dy = __fsub_rn(e0, s0), dx = __fsub_rn(e1, s1);
    float len = __fsqrt_rn(__fadd_rn(__fmul_rn(dy,dy), __fmul_rn(dx,dx)));
    float nsf = floorf(__fmul_rn(len, 0.125f));
    nsf = fminf(fmaxf(nsf, 2.0f), 5.0f);
    float inv = __fsub_rn(nsf, 1.0f);
    float i0 = __fdiv_rn(dy, inv);
    float i1 = __fdiv_rn(dx, inv);
    float kf = (float)k;
    bool valid = kf < nsf;
    float p0 = valid ? __fadd_rn(s0, __fmul_rn(kf, i0)) : 0.0f;
    float p1 = valid ? __fadd_rn(s1, __fmul_rn(kf, i1)) : 0.0f;

    float xn = __fsub_rn(__fdiv_rn(__fmul_rn(2.0f, p1), 511.0f), 1.0f);
    float yn = __fsub_rn(__fdiv_rn(__fmul_rn(2.0f, p0), 511.0f), 1.0f);
    float ix = __fmul_rn(__fsub_rn(__fmul_rn(__fadd_rn(xn,1.0f),(float)WW),1.0f), 0.5f);
    float iy = __fmul_rn(__fsub_rn(__fmul_rn(__fadd_rn(yn,1.0f),(float)HH),1.0f), 0.5f);
    float x0f = floorf(ix), y0f = floorf(iy);
    float wx = __fsub_rn(ix, x0f), wy = __fsub_rn(iy, y0f);
    int x0 = (int)x0f, y0 = (int)y0f;

    const float* img = (which == 0) ? g_desc1t : g_desc2t;
    auto G = [&](int xi, int yi) -> float {
        bool inb = (xi >= 0) && (xi < WW) && (yi >= 0) && (yi < HH);
        int xc = min(max(xi, 0), WW-1);
        int yc = min(max(yi, 0), HH-1);
        float v = img[(yc*WW + xc)*DIM + d];
        return inb ? v : 0.0f;
    };
    float w00 = __fmul_rn(__fsub_rn(1.0f,wx), __fsub_rn(1.0f,wy));
    float w10 = __fmul_rn(wx, __fsub_rn(1.0f,wy));
    float w01 = __fmul_rn(__fsub_rn(1.0f,wx), wy);
    float w11 = __fmul_rn(wx, wy);
    float v = __fadd_rn(__fadd_rn(__fadd_rn(
                __fmul_rn(G(x0,y0),w00), __fmul_rn(G(x0+1,y0),w10)),
                __fmul_rn(G(x0,y0+1),w01)), __fmul_rn(G(x0+1,y0+1),w11));

    float t = __fmul_rn(v,v);
    #pragma unroll
    for (int o = 16; o; o >>= 1) t = __fadd_rn(t, __shfl_xor_sync(0xffffffffu, t, o));
    __shared__ float red[4];
    __shared__ float tot;
    if ((threadIdx.x & 31) == 0) red[threadIdx.x >> 5] = t;
    __syncthreads();
    if (threadIdx.x == 0)
        tot = __fsqrt_rn(__fadd_rn(__fadd_rn(red[0],red[1]),__fadd_rn(red[2],red[3])));
    __syncthreads();

    float* dout = (which == 0) ? g_d1 : g_d2;
    dout[pid*DIM + d] = __fdiv_rn(v, tot);

    if (d == 0 && k == 0) {
        if (which == 0) g_ns1[line] = (int)nsf; else g_ns2[line] = (int)nsf;
    }
}

// ---------------- tiled transpose [pt][d] -> [d][pt] ----------------
__global__ void transpose_pts() {
    __shared__ float t[32][33];
    int p0 = blockIdx.x * 32, d0 = blockIdx.y * 32;
    const float* src = blockIdx.z ? g_d2 : g_d1;
    float* dst = blockIdx.z ? g_d2T : g_d1T;
    int tx = threadIdx.x, ty = threadIdx.y;   // 32 x 8
    #pragma unroll
    for (int r = 0; r < 32; r += 8) {
        int p = p0 + ty + r;
        if (p < NPTS) t[ty + r][tx] = src[p*DIM + d0 + tx];
    }
    __syncthreads();
    #pragma unroll
    for (int r = 0; r < 32; r += 8) {
        int d = d0 + ty + r;
        int p = p0 + tx;
        if (p < NPTS) dst[d*NPTS + p] = t[tx][ty + r];
    }
}

// ---------------- fused GEMM + line-score reduction ----------------
// K-major smem chunks (conflict-free LDS), cp.async double-buffered
__global__ __launch_bounds__(256, 3) void linescore_kernel() {
    __shared__ __align__(16) float As[2][KC][CPITCH];
    __shared__ __align__(16) float Bs[2][KC][CPITCH];
    int tid = threadIdx.x;
    int ti = tid >> 4;        // 0..15
    int tj = tid & 15;        // 0..15
    int ib = blockIdx.y * BT;
    int jb = blockIdx.x * BT;

    const float* AgT = g_d1T + ib*SAMP;   // + k*NPTS
    const float* BgT = g_d2T + jb*SAMP;
    uint32_t sbA = smem_u32(&As[0][0][0]);
    uint32_t sbB = smem_u32(&Bs[0][0][0]);

    // async-load one K-chunk: 32 k-rows x 80 floats per matrix (20 x 16B each)
    auto load_chunk = [&](int slot, int k0) {
        #pragma unroll
        for (int i = 0; i < 5; i++) {
            int idx = tid + i*256;            // 0..1279
            int isB = idx >= 640;
            int q   = isB ? idx - 640 : idx;  // 0..639
            int row = q / 20;
            int seg = q - row*20;
            uint32_t dst = (isB ? sbB : sbA)
                + (uint32_t)((slot*KC + row)*CPITCH + seg*4) * 4u;
            const float* src = (isB ? BgT : AgT) + (k0 + row)*NPTS + seg*4;
            CP_ASYNC16(dst, src);
        }
        CP_COMMIT();
    };

    float acc[5][5];
    #pragma unroll
    for (int s = 0; s < 5; s++)
        #pragma unroll
        for (int u = 0; u < 5; u++) acc[s][u] = 0.0f;

    load_chunk(0, 0);
    #pragma unroll
    for (int c = 0; c < 4; c++) {
        if (c < 3) { load_chunk((c+1)&1, (c+1)*KC); CP_WAIT1(); }
        else       { CP_WAIT0(); }
        __syncthreads();
        int sl = c & 1;
        #pragma unroll
        for (int k = 0; k < KC; k++) {
            float a[5], b[5];
            #pragma unroll
            for (int s = 0; s < 5; s++) a[s] = As[sl][k][ti*5+s];
            #pragma unroll
            for (int u = 0; u < 5; u++) b[u] = Bs[sl][k][tj*5+u];
            #pragma unroll
            for (int s = 0; s < 5; s++)
                #pragma unroll
                for (int u = 0; u < 5; u++) acc[s][u] += a[s]*b[u];
        }
        __syncthreads();
    }

    int i = ib + ti, j = jb + tj;
    int na = g_ns1[i], nb = g_ns2[j];

    float sc[5][5];
    #pragma unroll
    for (int s = 0; s < 5; s++)
        #pragma unroll
        for (int u = 0; u < 5; u++)
            sc[s][u] = (s < na && u < nb) ? acc[s][u] : -1.0f;

    float sum1 = 0.0f, c1 = 0.0f;
    #pragma unroll
    for (int s = 0; s < 5; s++) {
        float m = sc[s][0];
        #pragma unroll
        for (int u = 1; u < 5; u++) m = fmaxf(m, sc[s][u]);
        if (m != -1.0f) { sum1 += m; c1 += 1.0f; }
    }
    float sum2 = 0.0f, c2 = 0.0f;
    #pragma unroll
    for (int u = 0; u < 5; u++) {
        float m = sc[0][u];
        #pragma unroll
        for (int s = 1; s < 5; s++) m = fmaxf(m, sc[s][u]);
        if (m != -1.0f) { sum2 += m; c2 += 1.0f; }
    }
    float ls = (sum1/c1 + sum2/c2) * 0.5f;
    g_ls [i*N_LINES + j] = ls;
    g_lsT[j*N_LINES + i] = ls;
}

// ---------------- top-CAND candidate selection ----------------
__global__ void cand_kernel() {
    int row = blockIdx.x;
    int rev = blockIdx.y;
    int tid = threadIdx.x;
    int lane = tid & 31, warp = tid >> 5;
    __shared__ float vals[N_LINES];
    __shared__ float wv[8];
    __shared__ int   wi[8];

    const float* src = rev ? (g_lsT + row*N_LINES) : (g_ls + row*N_LINES);
    for (int j = tid; j < N_LINES; j += 256) vals[j] = src[j];
    __syncthreads();

    int* cand = rev ? g_candr : g_candf;
    for (int p = 0; p < CAND; p++) {
        float best = -1e30f; int bidx = -1;
        for (int j = tid; j < N_LINES; j += 256) {
            float v = vals[j];
            if (v > best || (v == best && j > bidx)) { best = v; bidx = j; }
        }
        #pragma unroll
        for (int o = 16; o; o >>= 1) {
            float ov = __shfl_xor_sync(0xffffffffu, best, o);
            int   oi = __shfl_xor_sync(0xffffffffu, bidx, o);
            if (ov > best || (ov == best && oi > bidx)) { best = ov; bidx = oi; }
        }
        if (lane == 0) { wv[warp] = best; wi[warp] = bidx; }
        __syncthreads();
        if (warp == 0) {
            best = (lane < 8) ? wv[lane] : -1e30f;
            bidx = (lane < 8) ? wi[lane] : -1;
            #pragma unroll
            for (int o = 4; o; o >>= 1) {
                float ov = __shfl_xor_sync(0xffffffffu, best, o);
                int   oi = __shfl_xor_sync(0xffffffffu, bidx, o);
                if (ov > best || (ov == best && oi > bidx)) { best = ov; bidx = oi; }
            }
            if (lane == 0) {
                cand[row*CAND + p] = bidx;
                vals[bidx] = -1e30f;
            }
        }
        __syncthreads();
    }
}

// ---------------- exact refinement with compensated dots ----------------
__global__ __launch_bounds__(128) void refine_kernel() {
    int r = blockIdx.x;
    int rev = blockIdx.y;
    int tid = threadIdx.x;
    __shared__ float F[5][DIM];
    __shared__ double dm[CAND][5][5];
    __shared__ double scs[CAND];
    __shared__ int cnd[CAND];

    if (tid < CAND) cnd[tid] = rev ? g_candr[r*CAND+tid] : g_candf[r*CAND+tid];
    const float* Ffix = rev ? (g_d2 + r*SAMP*DIM) : (g_d1 + r*SAMP*DIM);
    for (int idx = tid; idx < SAMP*DIM; idx += 128)
        F[idx/DIM][idx%DIM] = Ffix[idx];
    __syncthreads();

    if (tid < CAND*SAMP) {
        int c = tid / SAMP, v = tid % SAMP;
        int j = cnd[c];
        const float* Vg = rev ? (g_d1 + (j*SAMP+v)*DIM) : (g_d2 + (j*SAMP+v)*DIM);
        float s[5], comp[5];
        #pragma unroll
        for (int f = 0; f < 5; f++) { s[f] = 0.0f; comp[f] = 0.0f; }
        for (int k = 0; k < DIM; k++) {
            float b = Vg[k];
            #pragma unroll
            for (int f = 0; f < 5; f++) {
                float a = F[f][k];
                float p  = __fmul_rn(a, b);
                float ep = __fmaf_rn(a, b, -p);
                float t  = __fadd_rn(s[f], p);
                float z  = __fsub_rn(t, s[f]);
                float e  = __fadd_rn(__fsub_rn(s[f], __fsub_rn(t, z)),
                                     __fsub_rn(p, z));
                s[f] = t;
                comp[f] = __fadd_rn(comp[f], __fadd_rn(ep, e));
            }
        }
        #pragma unroll
        for (int f = 0; f < 5; f++) {
            double d = (double)s[f] + (double)comp[f];
            if (!rev) dm[c][f][v] = d;
            else      dm[c][v][f] = d;
        }
    }
    __syncthreads();

    if (tid < CAND) {
        int c = tid; int j = cnd[c];
        int na = rev ? g_ns1[j] : g_ns1[r];
        int nb = rev ? g_ns2[r] : g_ns2[j];
        double sum1 = 0.0, cc1 = 0.0, sum2 = 0.0, cc2 = 0.0;
        for (int a = 0; a < 5; a++) {
            double m = -1.0;
            for (int b = 0; b < 5; b++) {
                double val = (a < na && b < nb) ? dm[c][a][b] : -1.0;
                if (val > m) m = val;
            }
            if (a < na) { sum1 += m; cc1 += 1.0; }
        }
        for (int b = 0; b < 5; b++) {
            double m = -1.0;
            for (int a = 0; a < 5; a++) {
                double val = (a < na && b < nb) ? dm[c][a][b] : -1.0;
                if (val > m) m = val;
            }
            if (b < nb) { sum2 += m; cc2 += 1.0; }
        }
        scs[c] = (sum1/cc1 + sum2/cc2) * 0.5;
    }
    __syncthreads();

    if (tid == 0) {
        bool used[CAND];
        #pragma unroll
        for (int c = 0; c < CAND; c++) used[c] = false;
        int* out = rev ? &g_topkr[r*TOPK] : &g_topkf[r*TOPK];
        for (int p = 0; p < TOPK; p++) {
            double best = -1e300; int bidx = -1, bc = -1;
            for (int c = 0; c < CAND; c++) {
                if (used[c]) continue;
                double v = scs[c]; int idx = cnd[c];
                if (v > best || (v == best && idx > bidx)) { best = v; bidx = idx; bc = c; }
            }
            used[bc] = true;
            out[TOPK-1-p] = bidx;
        }
    }
}

// ---------------- Needleman-Wunsch ----------------
__device__ __forceinline__ float nw5(const float sc[5][5]) {
    float prev[6] = {0,0,0,0,0,0};
    #pragma unroll
    for (int r = 0; r < 5; r++) {
        float nr[6];
        nr[0] = 0.0f;
        float left = 0.0f;
        #pragma unroll
        for (int c = 0; c < 5; c++) {
            float cur = fmaxf(fmaxf(left, prev[c+1]), prev[c] + (sc[r][c] - GAPC));
            nr[c+1] = cur; left = cur;
        }
        #pragma unroll
        for (int c = 0; c < 6; c++) prev[c] = nr[c];
    }
    return prev[5];
}

__device__ __forceinline__ void dot_block(int i, int j, int na, int nb, float dm[5][5]) {
    const float4* pa = (const float4*)(g_d1 + i*SAMP*DIM);
    const float4* pb = (const float4*)(g_d2 + j*SAMP*DIM);
    float acc[5][5];
    #pragma unroll
    for (int a = 0; a < 5; a++)
        #pragma unroll
        for (int b = 0; b < 5; b++) acc[a][b] = 0.0f;
    for (int kk = 0; kk < DIM/4; kk++) {
        float4 x[5], y[5];
        #pragma unroll
        for (int a = 0; a < 5; a++) x[a] = pa[a*(DIM/4) + kk];
        #pragma unroll
        for (int b = 0; b < 5; b++) y[b] = pb[b*(DIM/4) + kk];
        #pragma unroll
        for (int a = 0; a < 5; a++)
            #pragma unroll
            for (int b = 0; b < 5; b++)
                acc[a][b] += x[a].x*y[b].x + x[a].y*y[b].y + x[a].z*y[b].z + x[a].w*y[b].w;
    }
    #pragma unroll
    for (int a = 0; a < 5; a++)
        #pragma unroll
        for (int b = 0; b < 5; b++)
            dm[a][b] = (a < na && b < nb) ? acc[a][b] : -1.0f;
}

// fused fwd+rev NW (grid.y selects direction)
__global__ void nw_kernel() {
    int id = blockIdx.x * blockDim.x + threadIdx.x;
    if (id >= N_LINES*2*TOPK) return;
    if (blockIdx.y == 0) {
        int i = id / (2*TOPK);
        int t = id % (2*TOPK);
        int j = g_topkf[i*TOPK + (t % TOPK)];
        float dm[5][5];
        dot_block(i, j, g_ns1[i], g_ns2[j], dm);
        if (t >= TOPK) {
            #pragma unroll
            for (int a = 0; a < 5; a++) {
                float tmp = dm[a][0]; dm[a][0] = dm[a][4]; dm[a][4] = tmp;
                tmp = dm[a][1]; dm[a][1] = dm[a][3]; dm[a][3] = tmp;
            }
        }
        g_nwf[id] = nw5(dm);
    } else {
        int j = id / (2*TOPK);
        int u = id % (2*TOPK);
        int i = g_topkr[j*TOPK + (u % TOPK)];
        float dm[5][5];
        dot_block(i, j, g_ns1[i], g_ns2[j], dm);
        float sc[5][5];
        #pragma unroll
        for (int b = 0; b < 5; b++)
            #pragma unroll
            for (int a = 0; a < 5; a++) sc[b][a] = dm[a][b];
        if (u >= TOPK) {
            #pragma unroll
            for (int b = 0; b < 5; b++) {
                float tmp = sc[b][0]; sc[b][0] = sc[b][4]; sc[b][4] = tmp;
                tmp = sc[b][1]; sc[b][1] = sc[b][3]; sc[b][3] = tmp;
            }
        }
        g_nwr[j*2*TOPK + u] = nw5(sc);
    }
}

__global__ void match_kernel() {
    int gi = blockIdx.x * blockDim.x + threadIdx.x;
    if (gi >= 2*N_LINES) return;
    int rev = gi >= N_LINES;
    int i = rev ? (gi - N_LINES) : gi;
    const float* nw = rev ? g_nwr : g_nwf;
    const int* topk = rev ? g_topkr : g_topkf;
    float best = nw[i*2*TOPK];
    int bt = 0;
    #pragma unroll
    for (int t = 1; t < 2*TOPK; t++) {
        float v = nw[i*2*TOPK + t];
        if (v > best) { best = v; bt = t; }
    }
    int m = topk[i*TOPK + (bt % TOPK)];
    if (rev) g_mr[i] = m; else g_mf[i] = m;
}

__global__ void finalize_kernel(void* out, int out_size) {
    int idx = blockIdx.x * blockDim.x + threadIdx.x;
    if (out_size >= N_LINES + N_LINES*2*TOPK) {
        float* o = (float*)out;
        if (idx < N_LINES) {
            int mf = g_mf[idx];
            o[idx] = (g_mr[mf] == idx) ? (float)mf : -1.0f;
        } else if (idx < N_LINES + N_LINES*2*TOPK) {
            o[idx] = g_nwf[idx - N_LINES];
        }
    } else if (out_size == N_LINES) {
        if (idx < N_LINES) {
            int mf = g_mf[idx];
            ((int*)out)[idx] = (g_mr[mf] == idx) ? mf : -1;
        }
    } else if (out_size == N_LINES*2*TOPK) {
        if (idx < N_LINES*2*TOPK) ((float*)out)[idx] = g_nwf[idx];
    }
}

// ---------------- launch ----------------
extern "C" void kernel_launch(void* const* d_in, const int* in_sizes, int n_in,
                              void* d_out, int out_size) {
    const float* seg1  = (const float*)d_in[0];
    const float* seg2  = (const float*)d_in[1];
    const float* desc1 = (const float*)d_in[2];
    const float* desc2 = (const float*)d_in[3];

    int tr_blocks = (2*HH*WW*DIM + 255) / 256;
    transpose_desc<<<tr_blocks, 256>>>(desc1, desc2);

    sample_kernel<<<NPTS, DIM>>>(seg1, 0);
    sample_kernel<<<NPTS, DIM>>>(seg2, 1);

    dim3 tp((NPTS + 31)/32, DIM/32, 2);
    transpose_pts<<<tp, dim3(32, 8)>>>();

    dim3 gs(N_LINES/BT, N_LINES/BT);
    linescore_kernel<<<gs, 256>>>();

    dim3 cg(N_LINES, 2);
    cand_kernel<<<cg, 256>>>();
    refine_kernel<<<cg, 128>>>();

    int nw_total = N_LINES*2*TOPK;
    dim3 ng((nw_total + 127)/128, 2);
    nw_kernel<<<ng, 128>>>();

    match_kernel<<<(2*N_LINES + 127)/128, 128>>>();

    int out_threads = N_LINES + N_LINES*2*TOPK;
    finalize_kernel<<<(out_threads + 255)/256, 256>>>(d_out, out_size);
}

// round 14
// speedup vs baseline: 1.2334x; 1.2334x over previous
#include <cuda_runtime.h>
#include <math.h>
#include <stdint.h>

#define N_LINES 1200
#define SAMP 5
#define NPTS (N_LINES*SAMP)     // 6000
#define DIM 128
#define HH 128
#define WW 128
#define HW (HH*WW)
#define TOPK 10
#define CAND 16
#define GAPC 0.1f
#define BT 16                    // lines per block edge
#define KC 32                    // K chunk
#define ROWS 80                  // BT*SAMP
#define PITCH 36                 // words per smem row (32 + 4 pad, 16B-aligned)

// ---------------- device scratch ----------------
__device__ float g_desc1t[HW*DIM];      // [y][x][d]
__device__ float g_desc2t[HW*DIM];
__device__ float g_d1[NPTS*DIM];        // sampled normalized descriptors [pt][d]
__device__ float g_d2[NPTS*DIM];
__device__ int   g_ns1[N_LINES];
__device__ int   g_ns2[N_LINES];
__device__ float g_ls [N_LINES*N_LINES];
__device__ float g_lsT[N_LINES*N_LINES];
__device__ int   g_candf[N_LINES*CAND];
__device__ int   g_candr[N_LINES*CAND];
__device__ int   g_topkf[N_LINES*TOPK];
__device__ int   g_topkr[N_LINES*TOPK];
__device__ float g_nwf[N_LINES*2*TOPK];
__device__ float g_nwr[N_LINES*2*TOPK];
__device__ int   g_mf[N_LINES];
__device__ int   g_mr[N_LINES];

__device__ __forceinline__ uint32_t smem_u32(const void* p) {
    uint32_t a;
    asm("{ .reg .u64 t; cvta.to.shared.u64 t, %1; cvt.u32.u64 %0, t; }" : "=r"(a) : "l"(p));
    return a;
}
#define CP_ASYNC16(dst, src) \
    asm volatile("cp.async.cg.shared.global [%0], [%1], 16;" :: "r"(dst), "l"(src) : "memory")
#define CP_COMMIT() asm volatile("cp.async.commit_group;" ::: "memory")
#define CP_WAIT0()  asm volatile("cp.async.wait_group 0;" ::: "memory")
#define CP_WAIT1()  asm volatile("cp.async.wait_group 1;" ::: "memory")

// ---------------- tiled transpose desc [d][p] -> [p][d], p = y*W+x ----------------
__global__ void transpose_desc(const float* __restrict__ in1, const float* __restrict__ in2) {
    __shared__ float t[32][33];
    int p0 = blockIdx.x * 32;        // HW direction
    int d0 = blockIdx.y * 32;        // DIM direction
    const float* in = blockIdx.z ? in2 : in1;
    float* out = blockIdx.z ? g_desc2t : g_desc1t;
    int tx = threadIdx.x, ty = threadIdx.y;   // 32 x 8
    #pragma unroll
    for (int r = 0; r < 32; r += 8)
        t[ty + r][tx] = in[(d0 + ty + r)*HW + p0 + tx];
    __syncthreads();
    #pragma unroll
    for (int r = 0; r < 32; r += 8)
        out[(p0 + ty + r)*DIM + d0 + tx] = t[tx][ty + r];
}

// ---------------- sample points + bilinear descriptors + normalize ----------------
__global__ void sample_kernel(const float* __restrict__ seg, int which) {
    int pid  = blockIdx.x;            // 0..NPTS-1
    int line = pid / SAMP;
    int k    = pid % SAMP;
    int d    = threadIdx.x;           // 0..127

    float s0 = seg[line*4+0], s1 = seg[line*4+1];
    float e0 = seg[line*4+2], e1 = seg[line*4+3];
    float dy = __fsub_rn(e0, s0), dx = __fsub_rn(e1, s1);
    float len = __fsqrt_rn(__fadd_rn(__fmul_rn(dy,dy), __fmul_rn(dx,dx)));
    float nsf = floorf(__fmul_rn(len, 0.125f));
    nsf = fminf(fmaxf(nsf, 2.0f), 5.0f);
    float inv = __fsub_rn(nsf, 1.0f);
    float i0 = __fdiv_rn(dy, inv);
    float i1 = __fdiv_rn(dx, inv);
    float kf = (float)k;
    bool valid = kf < nsf;
    float p0 = valid ? __fadd_rn(s0, __fmul_rn(kf, i0)) : 0.0f;
    float p1 = valid ? __fadd_rn(s1, __fmul_rn(kf, i1)) : 0.0f;

    float xn = __fsub_rn(__fdiv_rn(__fmul_rn(2.0f, p1), 511.0f), 1.0f);
    float yn = __fsub_rn(__fdiv_rn(__fmul_rn(2.0f, p0), 511.0f), 1.0f);
    float ix = __fmul_rn(__fsub_rn(__fmul_rn(__fadd_rn(xn,1.0f),(float)WW),1.0f), 0.5f);
    float iy = __fmul_rn(__fsub_rn(__fmul_rn(__fadd_rn(yn,1.0f),(float)HH),1.0f), 0.5f);
    float x0f = floorf(ix), y0f = floorf(iy);
    float wx = __fsub_rn(ix, x0f), wy = __fsub_rn(iy, y0f);
    int x0 = (int)x0f, y0 = (int)y0f;

    const float* img = (which == 0) ? g_desc1t : g_desc2t;
    auto G = [&](int xi, int yi) -> float {
        bool inb = (xi >= 0) && (xi < WW) && (yi >= 0) && (yi < HH);
        int xc = min(max(xi, 0), WW-1);
        int yc = min(max(yi, 0), HH-1);
        float v = img[(yc*WW + xc)*DIM + d];
        return inb ? v : 0.0f;
    };
    float w00 = __fmul_rn(__fsub_rn(1.0f,wx), __fsub_rn(1.0f,wy));
    float w10 = __fmul_rn(wx, __fsub_rn(1.0f,wy));
    float w01 = __fmul_rn(__fsub_rn(1.0f,wx), wy);
    float w11 = __fmul_rn(wx, wy);
    float v = __fadd_rn(__fadd_rn(__fadd_rn(
                __fmul_rn(G(x0,y0),w00), __fmul_rn(G(x0+1,y0),w10)),
                __fmul_rn(G(x0,y0+1),w01)), __fmul_rn(G(x0+1,y0+1),w11));

    float t = __fmul_rn(v,v);
    #pragma unroll
    for (int o = 16; o; o >>= 1) t = __fadd_rn(t, __shfl_xor_sync(0xffffffffu, t, o));
    __shared__ float red[4];
    __shared__ float tot;
    if ((threadIdx.x & 31) == 0) red[threadIdx.x >> 5] = t;
    __syncthreads();
    if (threadIdx.x == 0)
        tot = __fsqrt_rn(__fadd_rn(__fadd_rn(red[0],red[1]),__fadd_rn(red[2],red[3])));
    __syncthreads();

    float* dout = (which == 0) ? g_d1 : g_d2;
    dout[pid*DIM + d] = __fdiv_rn(v, tot);

    if (d == 0 && k == 0) {
        if (which == 0) g_ns1[line] = (int)nsf; else g_ns2[line] = (int)nsf;
    }
}

// ---------------- fused GEMM + line-score reduction (R10 layout, float4 LDS) ----------------
__global__ __launch_bounds__(256) void linescore_kernel() {
    __shared__ __align__(16) float As[2][ROWS][PITCH];
    __shared__ __align__(16) float Bs[2][ROWS][PITCH];
    int tid = threadIdx.x;
    int ti = tid >> 4;        // 0..15
    int tj = tid & 15;        // 0..15
    int ib = blockIdx.y * BT;
    int jb = blockIdx.x * BT;

    const float* Ag = g_d1 + (ib*SAMP)*DIM;
    const float* Bg = g_d2 + (jb*SAMP)*DIM;
    uint32_t sbA = smem_u32(&As[0][0][0]);
    uint32_t sbB = smem_u32(&Bs[0][0][0]);

    // async-load one K-chunk into a slot: 80 rows x 32 floats each matrix
    auto load_chunk = [&](int slot, int k0) {
        #pragma unroll
        for (int i = 0; i < 5; i++) {
            int idx = tid + i*256;          // 0..1279
            int isB = idx >= 640;
            int r   = (idx - (isB ? 640 : 0)) >> 3;
            int cs  = idx & 7;              // 16B segment within 32 floats
            uint32_t dst = (isB ? sbB : sbA)
                + (uint32_t)((slot*ROWS + r)*PITCH + cs*4) * 4u;
            const float* src = (isB ? Bg : Ag) + r*DIM + k0 + cs*4;
            CP_ASYNC16(dst, src);
        }
        CP_COMMIT();
    };

    float acc[5][5];
    #pragma unroll
    for (int s = 0; s < 5; s++)
        #pragma unroll
        for (int u = 0; u < 5; u++) acc[s][u] = 0.0f;

    load_chunk(0, 0);
    #pragma unroll
    for (int c = 0; c < 4; c++) {
        if (c < 3) { load_chunk((c+1)&1, (c+1)*KC); CP_WAIT1(); }
        else       { CP_WAIT0(); }
        __syncthreads();
        int sl = c & 1;
        #pragma unroll
        for (int k4 = 0; k4 < KC/4; k4++) {
            float4 a4[5], b4[5];
            #pragma unroll
            for (int s = 0; s < 5; s++)
                a4[s] = *(const float4*)&As[sl][ti*5+s][k4*4];
            #pragma unroll
            for (int u = 0; u < 5; u++)
                b4[u] = *(const float4*)&Bs[sl][tj*5+u][k4*4];
            #pragma unroll
            for (int s = 0; s < 5; s++)
                #pragma unroll
                for (int u = 0; u < 5; u++) {
                    // k-ascending order: bit-identical to scalar version
                    acc[s][u] += a4[s].x*b4[u].x;
                    acc[s][u] += a4[s].y*b4[u].y;
                    acc[s][u] += a4[s].z*b4[u].z;
                    acc[s][u] += a4[s].w*b4[u].w;
                }
        }
        __syncthreads();
    }

    int i = ib + ti, j = jb + tj;
    int na = g_ns1[i], nb = g_ns2[j];

    float sc[5][5];
    #pragma unroll
    for (int s = 0; s < 5; s++)
        #pragma unroll
        for (int u = 0; u < 5; u++)
            sc[s][u] = (s < na && u < nb) ? acc[s][u] : -1.0f;

    float sum1 = 0.0f, c1 = 0.0f;
    #pragma unroll
    for (int s = 0; s < 5; s++) {
        float m = sc[s][0];
        #pragma unroll
        for (int u = 1; u < 5; u++) m = fmaxf(m, sc[s][u]);
        if (m != -1.0f) { sum1 += m; c1 += 1.0f; }
    }
    float sum2 = 0.0f, c2 = 0.0f;
    #pragma unroll
    for (int u = 0; u < 5; u++) {
        float m = sc[0][u];
        #pragma unroll
        for (int s = 1; s < 5; s++) m = fmaxf(m, sc[s][u]);
        if (m != -1.0f) { sum2 += m; c2 += 1.0f; }
    }
    float ls = (sum1/c1 + sum2/c2) * 0.5f;
    g_ls [i*N_LINES + j] = ls;
    g_lsT[j*N_LINES + i] = ls;
}

// ---------------- top-CAND candidate selection ----------------
__global__ void cand_kernel() {
    int row = blockIdx.x;
    int rev = blockIdx.y;
    int tid = threadIdx.x;
    int lane = tid & 31, warp = tid >> 5;
    __shared__ float vals[N_LINES];
    __shared__ float wv[8];
    __shared__ int   wi[8];

    const float* src = rev ? (g_lsT + row*N_LINES) : (g_ls + row*N_LINES);
    for (int j = tid; j < N_LINES; j += 256) vals[j] = src[j];
    __syncthreads();

    int* cand = rev ? g_candr : g_candf;
    for (int p = 0; p < CAND; p++) {
        float best = -1e30f; int bidx = -1;
        for (int j = tid; j < N_LINES; j += 256) {
            float v = vals[j];
            if (v > best || (v == best && j > bidx)) { best = v; bidx = j; }
        }
        #pragma unroll
        for (int o = 16; o; o >>= 1) {
            float ov = __shfl_xor_sync(0xffffffffu, best, o);
            int   oi = __shfl_xor_sync(0xffffffffu, bidx, o);
            if (ov > best || (ov == best && oi > bidx)) { best = ov; bidx = oi; }
        }
        if (lane == 0) { wv[warp] = best; wi[warp] = bidx; }
        __syncthreads();
        if (warp == 0) {
            best = (lane < 8) ? wv[lane] : -1e30f;
            bidx = (lane < 8) ? wi[lane] : -1;
            #pragma unroll
            for (int o = 4; o; o >>= 1) {
                float ov = __shfl_xor_sync(0xffffffffu, best, o);
                int   oi = __shfl_xor_sync(0xffffffffu, bidx, o);
                if (ov > best || (ov == best && oi > bidx)) { best = ov; bidx = oi; }
            }
            if (lane == 0) {
                cand[row*CAND + p] = bidx;
                vals[bidx] = -1e30f;
            }
        }
        __syncthreads();
    }
}

// ---------------- exact refinement with compensated dots (float4 global loads) ----------------
__global__ __launch_bounds__(128) void refine_kernel() {
    int r = blockIdx.x;
    int rev = blockIdx.y;
    int tid = threadIdx.x;
    __shared__ float F[5][DIM];
    __shared__ double dm[CAND][5][5];
    __shared__ double scs[CAND];
    __shared__ int cnd[CAND];

    if (tid < CAND) cnd[tid] = rev ? g_candr[r*CAND+tid] : g_candf[r*CAND+tid];
    const float* Ffix = rev ? (g_d2 + r*SAMP*DIM) : (g_d1 + r*SAMP*DIM);
    for (int idx = tid; idx < SAMP*DIM; idx += 128)
        F[idx/DIM][idx%DIM] = Ffix[idx];
    __syncthreads();

    if (tid < CAND*SAMP) {
        int c = tid / SAMP, v = tid % SAMP;
        int j = cnd[c];
        const float4* Vg = (const float4*)(rev ? (g_d1 + (j*SAMP+v)*DIM)
                                               : (g_d2 + (j*SAMP+v)*DIM));
        float s[5], comp[5];
        #pragma unroll
        for (int f = 0; f < 5; f++) { s[f] = 0.0f; comp[f] = 0.0f; }
        for (int k4 = 0; k4 < DIM/4; k4++) {
            float4 bq = Vg[k4];
            float bv[4] = {bq.x, bq.y, bq.z, bq.w};
            #pragma unroll
            for (int q = 0; q < 4; q++) {
                float b = bv[q];
                int k = k4*4 + q;
                #pragma unroll
                for (int f = 0; f < 5; f++) {
                    float a = F[f][k];
                    float p  = __fmul_rn(a, b);
                    float ep = __fmaf_rn(a, b, -p);
                    float t  = __fadd_rn(s[f], p);
                    float z  = __fsub_rn(t, s[f]);
                    float e  = __fadd_rn(__fsub_rn(s[f], __fsub_rn(t, z)),
                                         __fsub_rn(p, z));
                    s[f] = t;
                    comp[f] = __fadd_rn(comp[f], __fadd_rn(ep, e));
                }
            }
        }
        #pragma unroll
        for (int f = 0; f < 5; f++) {
            double d = (double)s[f] + (double)comp[f];
            if (!rev) dm[c][f][v] = d;
            else      dm[c][v][f] = d;
        }
    }
    __syncthreads();

    if (tid < CAND) {
        int c = tid; int j = cnd[c];
        int na = rev ? g_ns1[j] : g_ns1[r];
        int nb = rev ? g_ns2[r] : g_ns2[j];
        double sum1 = 0.0, cc1 = 0.0, sum2 = 0.0, cc2 = 0.0;
        for (int a = 0; a < 5; a++) {
            double m = -1.0;
            for (int b = 0; b < 5; b++) {
                double val = (a < na && b < nb) ? dm[c][a][b] : -1.0;
                if (val > m) m = val;
            }
            if (a < na) { sum1 += m; cc1 += 1.0; }
        }
        for (int b = 0; b < 5; b++) {
            double m = -1.0;
            for (int a = 0; a < 5; a++) {
                double val = (a < na && b < nb) ? dm[c][a][b] : -1.0;
                if (val > m) m = val;
            }
            if (b < nb) { sum2 += m; cc2 += 1.0; }
        }
        scs[c] = (sum1/cc1 + sum2/cc2) * 0.5;
    }
    __syncthreads();

    if (tid == 0) {
        bool used[CAND];
        #pragma unroll
        for (int c = 0; c < CAND; c++) used[c] = false;
        int* out = rev ? &g_topkr[r*TOPK] : &g_topkf[r*TOPK];
        for (int p = 0; p < TOPK; p++) {
            double best = -1e300; int bidx = -1, bc = -1;
            for (int c = 0; c < CAND; c++) {
                if (used[c]) continue;
                double v = scs[c]; int idx = cnd[c];
                if (v > best || (v == best && idx > bidx)) { best = v; bidx = idx; bc = c; }
            }
            used[bc] = true;
            out[TOPK-1-p] = bidx;
        }
    }
}

// ---------------- Needleman-Wunsch ----------------
__device__ __forceinline__ float nw5(const float sc[5][5]) {
    float prev[6] = {0,0,0,0,0,0};
    #pragma unroll
    for (int r = 0; r < 5; r++) {
        float nr[6];
        nr[0] = 0.0f;
        float left = 0.0f;
        #pragma unroll
        for (int c = 0; c < 5; c++) {
            float cur = fmaxf(fmaxf(left, prev[c+1]), prev[c] + (sc[r][c] - GAPC));
            nr[c+1] = cur; left = cur;
        }
        #pragma unroll
        for (int c = 0; c < 6; c++) prev[c] = nr[c];
    }
    return prev[5];
}

__device__ __forceinline__ void dot_block(int i, int j, int na, int nb, float dm[5][5]) {
    const float4* pa = (const float4*)(g_d1 + i*SAMP*DIM);
    const float4* pb = (const float4*)(g_d2 + j*SAMP*DIM);
    float acc[5][5];
    #pragma unroll
    for (int a = 0; a < 5; a++)
        #pragma unroll
        for (int b = 0; b < 5; b++) acc[a][b] = 0.0f;
    for (int kk = 0; kk < DIM/4; kk++) {
        float4 x[5], y[5];
        #pragma unroll
        for (int a = 0; a < 5; a++) x[a] = pa[a*(DIM/4) + kk];
        #pragma unroll
        for (int b = 0; b < 5; b++) y[b] = pb[b*(DIM/4) + kk];
        #pragma unroll
        for (int a = 0; a < 5; a++)
            #pragma unroll
            for (int b = 0; b < 5; b++)
                acc[a][b] += x[a].x*y[b].x + x[a].y*y[b].y + x[a].z*y[b].z + x[a].w*y[b].w;
    }
    #pragma unroll
    for (int a = 0; a < 5; a++)
        #pragma unroll
        for (int b = 0; b < 5; b++)
            dm[a][b] = (a < na && b < nb) ? acc[a][b] : -1.0f;
}

// fused fwd+rev NW (grid.y selects direction)
__global__ void nw_kernel() {
    int id = blockIdx.x * blockDim.x + threadIdx.x;
    if (id >= N_LINES*2*TOPK) return;
    if (blockIdx.y == 0) {
        int i = id / (2*TOPK);
        int t = id % (2*TOPK);
        int j = g_topkf[i*TOPK + (t % TOPK)];
        float dm[5][5];
        dot_block(i, j, g_ns1[i], g_ns2[j], dm);
        if (t >= TOPK) {
            #pragma unroll
            for (int a = 0; a < 5; a++) {
                float tmp = dm[a][0]; dm[a][0] = dm[a][4]; dm[a][4] = tmp;
                tmp = dm[a][1]; dm[a][1] = dm[a][3]; dm[a][3] = tmp;
            }
        }
        g_nwf[id] = nw5(dm);
    } else {
        int j = id / (2*TOPK);
        int u = id % (2*TOPK);
        int i = g_topkr[j*TOPK + (u % TOPK)];
        float dm[5][5];
        dot_block(i, j, g_ns1[i], g_ns2[j], dm);
        float sc[5][5];
        #pragma unroll
        for (int b = 0; b < 5; b++)
            #pragma unroll
            for (int a = 0; a < 5; a++) sc[b][a] = dm[a][b];
        if (u >= TOPK) {
            #pragma unroll
            for (int b = 0; b < 5; b++) {
                float tmp = sc[b][0]; sc[b][0] = sc[b][4]; sc[b][4] = tmp;
                tmp = sc[b][1]; sc[b][1] = sc[b][3]; sc[b][3] = tmp;
            }
        }
        g_nwr[j*2*TOPK + u] = nw5(sc);
    }
}

__global__ void match_kernel() {
    int gi = blockIdx.x * blockDim.x + threadIdx.x;
    if (gi >= 2*N_LINES) return;
    int rev = gi >= N_LINES;
    int i = rev ? (gi - N_LINES) : gi;
    const float* nw = rev ? g_nwr : g_nwf;
    const int* topk = rev ? g_topkr : g_topkf;
    float best = nw[i*2*TOPK];
    int bt = 0;
    #pragma unroll
    for (int t = 1; t < 2*TOPK; t++) {
        float v = nw[i*2*TOPK + t];
        if (v > best) { best = v; bt = t; }
    }
    int m = topk[i*TOPK + (bt % TOPK)];
    if (rev) g_mr[i] = m; else g_mf[i] = m;
}

__global__ void finalize_kernel(void* out, int out_size) {
    int idx = blockIdx.x * blockDim.x + threadIdx.x;
    if (out_size >= N_LINES + N_LINES*2*TOPK) {
        float* o = (float*)out;
        if (idx < N_LINES) {
            int mf = g_mf[idx];
            o[idx] = (g_mr[mf] == idx) ? (float)mf : -1.0f;
        } else if (idx < N_LINES + N_LINES*2*TOPK) {
            o[idx] = g_nwf[idx - N_LINES];
        }
    } else if (out_size == N_LINES) {
        if (idx < N_LINES) {
            int mf = g_mf[idx];
            ((int*)out)[idx] = (g_mr[mf] == idx) ? mf : -1;
        }
    } else if (out_size == N_LINES*2*TOPK) {
        if (idx < N_LINES*2*TOPK) ((float*)out)[idx] = g_nwf[idx];
    }
}

// ---------------- launch ----------------
extern "C" void kernel_launch(void* const* d_in, const int* in_sizes, int n_in,
                              void* d_out, int out_size) {
    const float* seg1  = (const float*)d_in[0];
    const float* seg2  = (const float*)d_in[1];
    const float* desc1 = (const float*)d_in[2];
    const float* desc2 = (const float*)d_in[3];

    dim3 tg(HW/32, DIM/32, 2);
    transpose_desc<<<tg, dim3(32, 8)>>>(desc1, desc2);

    sample_kernel<<<NPTS, DIM>>>(seg1, 0);
    sample_kernel<<<NPTS, DIM>>>(seg2, 1);

    dim3 gs(N_LINES/BT, N_LINES/BT);
    linescore_kernel<<<gs, 256>>>();

    dim3 cg(N_LINES, 2);
    cand_kernel<<<cg, 256>>>();
    refine_kernel<<<cg, 128>>>();

    int nw_total = N_LINES*2*TOPK;
    dim3 ng((nw_total + 127)/128, 2);
    nw_kernel<<<ng, 128>>>();

    match_kernel<<<(2*N_LINES + 127)/128, 128>>>();

    int out_threads = N_LINES + N_LINES*2*TOPK;
    finalize_kernel<<<(out_threads + 255)/256, 256>>>(d_out, out_size);
}